// round 6
// baseline (speedup 1.0000x reference)
#include <cuda_runtime.h>

// Fused HybridSamplerConv, round 5: ONE graph node + occupancy recovery.
// R4 analysis: 31 live param regs pushed regs to 64 -> occ 41% -> DRAM 62%.
// Fix: __launch_bounds__(256, 6) caps regs at 42; ptxas rematerializes the
// uniform L1-hit param loads near use instead of keeping them all live.

__device__ __forceinline__ float tanh_fast(float x) {
    float y;
    asm("tanh.approx.f32 %0, %1;" : "=f"(y) : "f"(x));
    return y;
}

__global__ void __launch_bounds__(256, 6)
hybrid_sampler_kernel(const float4* __restrict__ inp,    // [B/2]: 2 samples per float4
                      const float4* __restrict__ data,   // [B]:   1 sample per float4
                      const float4* __restrict__ conv_w, // 4 floats
                      const float*  __restrict__ conv_b, // 1 float
                      const float4* __restrict__ w1v,    // 12 floats = 3 x float4 (rows)
                      const float4* __restrict__ b1v,    // 4 floats
                      const float4* __restrict__ w2v,    // 8 floats = 2 x float4
                      const float2* __restrict__ b2v,    // 2 floats
                      float4*       __restrict__ out,    // [B/2]
                      int nquads)                        // B/4
{
    int i = blockIdx.x * blockDim.x + threadIdx.x;
    if (i >= nquads) return;

    // --- streaming loads first: 6x 128-bit, front-batched (MLP_p1 = 6) ---
    float4 inA = inp[2 * i + 0];
    float4 inB = inp[2 * i + 1];
    float4 d0  = data[4 * i + 0];
    float4 d1  = data[4 * i + 1];
    float4 d2  = data[4 * i + 2];
    float4 d3  = data[4 * i + 3];

    // --- uniform parameter loads: L1-broadcast, rematerializable under the
    //     register cap (pure loads, no dependent arithmetic) ---
    float4 cw  = __ldg(conv_w);
    float  cb  = __ldg(conv_b);
    float4 w1r0 = __ldg(w1v + 0);   // w1[0][0..3] (in0 weights)
    float4 w1r1 = __ldg(w1v + 1);   // w1[1][0..3] (in1 weights)
    float4 w1r2 = __ldg(w1v + 2);   // w1[2][0..3] (conv weights)
    float4 b1   = __ldg(b1v);
    float4 w2a  = __ldg(w2v + 0);   // (w2[0][0], w2[0][1], w2[1][0], w2[1][1])
    float4 w2b  = __ldg(w2v + 1);   // (w2[2][0], w2[2][1], w2[3][0], w2[3][1])
    float2 b2   = __ldg(b2v);

    float4 resA, resB;

#pragma unroll
    for (int s = 0; s < 4; ++s) {
        float in0, in1;
        float4 d;
        if      (s == 0) { in0 = inA.x; in1 = inA.y; d = d0; }
        else if (s == 1) { in0 = inA.z; in1 = inA.w; d = d1; }
        else if (s == 2) { in0 = inB.x; in1 = inB.y; d = d2; }
        else             { in0 = inB.z; in1 = inB.w; d = d3; }

        // conv 2x2 -> sigmoid (THRESHOLD = 0)
        float logit = fmaf(d.x, cw.x, fmaf(d.y, cw.y,
                      fmaf(d.z, cw.z, fmaf(d.w, cw.w, cb))));
        float conv = 1.0f / (1.0f + __expf(-logit));

        // h = tanh([in0, in1, conv] @ w1 + b1)
        float h0 = tanh_fast(fmaf(in0, w1r0.x, fmaf(in1, w1r1.x, fmaf(conv, w1r2.x, b1.x))));
        float h1 = tanh_fast(fmaf(in0, w1r0.y, fmaf(in1, w1r1.y, fmaf(conv, w1r2.y, b1.y))));
        float h2 = tanh_fast(fmaf(in0, w1r0.z, fmaf(in1, w1r1.z, fmaf(conv, w1r2.z, b1.z))));
        float h3 = tanh_fast(fmaf(in0, w1r0.w, fmaf(in1, w1r1.w, fmaf(conv, w1r2.w, b1.w))));

        // z = h @ w2 + b2
        float z0 = fmaf(h0, w2a.x, fmaf(h1, w2a.z, fmaf(h2, w2b.x, fmaf(h3, w2b.z, b2.x))));
        float z1 = fmaf(h0, w2a.y, fmaf(h1, w2a.w, fmaf(h2, w2b.y, fmaf(h3, w2b.w, b2.y))));

        // softmax over 2 (exact, symmetric)
        float e = __expf(z1 - z0);
        float r = 1.0f / (1.0f + e);
        float o0 = r, o1 = e * r;

        if      (s == 0) { resA.x = o0; resA.y = o1; }
        else if (s == 1) { resA.z = o0; resA.w = o1; }
        else if (s == 2) { resB.x = o0; resB.y = o1; }
        else             { resB.z = o0; resB.w = o1; }
    }

    out[2 * i + 0] = resA;
    out[2 * i + 1] = resB;
}

extern "C" void kernel_launch(void* const* d_in, const int* in_sizes, int n_in,
                              void* d_out, int out_size)
{
    const float* inp    = (const float*)d_in[0]; // [B,2]
    const float* data   = (const float*)d_in[1]; // [B,2,2]
    const float* conv_w = (const float*)d_in[2]; // [2,2]
    const float* conv_b = (const float*)d_in[3]; // scalar
    const float* w1     = (const float*)d_in[4]; // [3,4]
    const float* b1     = (const float*)d_in[5]; // [4]
    const float* w2     = (const float*)d_in[6]; // [4,2]
    const float* b2     = (const float*)d_in[7]; // [2]
    float* out          = (float*)d_out;         // [B,2]

    int B = in_sizes[0] / 2;   // samples
    int nquads = B / 4;        // 4 samples per thread

    int threads = 256;
    int blocks = (nquads + threads - 1) / threads;

    hybrid_sampler_kernel<<<blocks, threads>>>(
        (const float4*)inp, (const float4*)data,
        (const float4*)conv_w, conv_b,
        (const float4*)w1, (const float4*)b1,
        (const float4*)w2, (const float2*)b2,
        (float4*)out, nquads);
}

// round 7
// speedup vs baseline: 1.1464x; 1.1464x over previous
#include <cuda_runtime.h>

// Fused HybridSamplerConv, round 6: ONE graph node, params staged in SMEM.
// R5 lesson: reg-capping 31 LDG-sourced params makes ptxas spill (30.2us).
// R2 lesson: kernel hits ~20us when params are NOT register-resident.
// Fix: block-cooperative param load into shared memory; LDS reads are cheap
// to schedule near use without pinning 31 registers. No launch_bounds cap.

__device__ __forceinline__ float tanh_fast(float x) {
    float y;
    asm("tanh.approx.f32 %0, %1;" : "=f"(y) : "f"(x));
    return y;
}

// smem param layout:
//  [0..3]  conv_w      [4] conv_b
//  [5..16] w1 (3x4 row-major)
//  [17..20] b1
//  [21..28] w2 (4x2 row-major)
//  [29..30] b2
__global__ void __launch_bounds__(256)
hybrid_sampler_kernel(const float4* __restrict__ inp,    // [B/2]
                      const float4* __restrict__ data,   // [B]
                      const float*  __restrict__ conv_w,
                      const float*  __restrict__ conv_b,
                      const float*  __restrict__ w1,
                      const float*  __restrict__ b1,
                      const float*  __restrict__ w2,
                      const float*  __restrict__ b2,
                      float4*       __restrict__ out,    // [B/2]
                      int nquads)                        // B/4
{
    __shared__ float sp[32];

    int t = threadIdx.x;
    if (t < 31) {
        float v;
        if      (t < 4)  v = conv_w[t];
        else if (t == 4) v = conv_b[0];
        else if (t < 17) v = w1[t - 5];
        else if (t < 21) v = b1[t - 17];
        else if (t < 29) v = w2[t - 21];
        else             v = b2[t - 29];
        sp[t] = v;
    }

    int i = blockIdx.x * blockDim.x + t;

    // Streaming loads first: 6x 128-bit, front-batched (MLP_p1 = 6).
    // Issued before the barrier so they overlap the param staging.
    float4 inA, inB, d0, d1, d2, d3;
    bool active = (i < nquads);
    if (active) {
        inA = inp[2 * i + 0];
        inB = inp[2 * i + 1];
        d0  = data[4 * i + 0];
        d1  = data[4 * i + 1];
        d2  = data[4 * i + 2];
        d3  = data[4 * i + 3];
    }

    __syncthreads();

    if (!active) return;

    float4 resA, resB;

#pragma unroll
    for (int s = 0; s < 4; ++s) {
        float in0, in1;
        float4 d;
        if      (s == 0) { in0 = inA.x; in1 = inA.y; d = d0; }
        else if (s == 1) { in0 = inA.z; in1 = inA.w; d = d1; }
        else if (s == 2) { in0 = inB.x; in1 = inB.y; d = d2; }
        else             { in0 = inB.z; in1 = inB.w; d = d3; }

        // conv 2x2 -> sigmoid (THRESHOLD = 0)
        float logit = fmaf(d.x, sp[0], fmaf(d.y, sp[1],
                      fmaf(d.z, sp[2], fmaf(d.w, sp[3], sp[4]))));
        float conv = 1.0f / (1.0f + __expf(-logit));

        // h = tanh([in0, in1, conv] @ w1 + b1)
        float h0 = tanh_fast(fmaf(in0, sp[5 + 0], fmaf(in1, sp[5 + 4], fmaf(conv, sp[5 + 8],  sp[17]))));
        float h1 = tanh_fast(fmaf(in0, sp[5 + 1], fmaf(in1, sp[5 + 5], fmaf(conv, sp[5 + 9],  sp[18]))));
        float h2 = tanh_fast(fmaf(in0, sp[5 + 2], fmaf(in1, sp[5 + 6], fmaf(conv, sp[5 + 10], sp[19]))));
        float h3 = tanh_fast(fmaf(in0, sp[5 + 3], fmaf(in1, sp[5 + 7], fmaf(conv, sp[5 + 11], sp[20]))));

        // z = h @ w2 + b2   (w2 row-major [4,2] at sp[21..28])
        float z0 = fmaf(h0, sp[21], fmaf(h1, sp[23], fmaf(h2, sp[25], fmaf(h3, sp[27], sp[29]))));
        float z1 = fmaf(h0, sp[22], fmaf(h1, sp[24], fmaf(h2, sp[26], fmaf(h3, sp[28], sp[30]))));

        // softmax over 2 (exact, symmetric)
        float e = __expf(z1 - z0);
        float r = 1.0f / (1.0f + e);
        float o0 = r, o1 = e * r;

        if      (s == 0) { resA.x = o0; resA.y = o1; }
        else if (s == 1) { resA.z = o0; resA.w = o1; }
        else if (s == 2) { resB.x = o0; resB.y = o1; }
        else             { resB.z = o0; resB.w = o1; }
    }

    out[2 * i + 0] = resA;
    out[2 * i + 1] = resB;
}

extern "C" void kernel_launch(void* const* d_in, const int* in_sizes, int n_in,
                              void* d_out, int out_size)
{
    const float* inp    = (const float*)d_in[0]; // [B,2]
    const float* data   = (const float*)d_in[1]; // [B,2,2]
    const float* conv_w = (const float*)d_in[2];
    const float* conv_b = (const float*)d_in[3];
    const float* w1     = (const float*)d_in[4];
    const float* b1     = (const float*)d_in[5];
    const float* w2     = (const float*)d_in[6];
    const float* b2     = (const float*)d_in[7];
    float* out          = (float*)d_out;

    int B = in_sizes[0] / 2;   // samples
    int nquads = B / 4;        // 4 samples per thread

    int threads = 256;
    int blocks = (nquads + threads - 1) / threads;

    hybrid_sampler_kernel<<<blocks, threads>>>(
        (const float4*)inp, (const float4*)data,
        conv_w, conv_b, w1, b1, w2, b2,
        (float4*)out, nquads);
}

// round 8
// speedup vs baseline: 1.2276x; 1.0708x over previous
#include <cuda_runtime.h>

// Fused HybridSamplerConv, round 7: ONE graph node (R4 structure) + algebraic
// shrink:
//  - softmax-of-2 folded to logit DIFFERENCE: only 4 delta weights g[] and
//    scalar gb survive (w2,b2 die after a one-time fold) -> 5 fewer live regs,
//    5 fewer FMAs/sample.
//  - conv sigmoid via tanh identity (1 MUFU instead of exp+rcp).

__device__ __forceinline__ float tanh_fast(float x) {
    float y;
    asm("tanh.approx.f32 %0, %1;" : "=f"(y) : "f"(x));
    return y;
}

__global__ void __launch_bounds__(256)
hybrid_sampler_kernel(const float4* __restrict__ inp,    // [B/2]: 2 samples per float4
                      const float4* __restrict__ data,   // [B]:   1 sample per float4
                      const float4* __restrict__ conv_w, // 4 floats
                      const float*  __restrict__ conv_b, // 1 float
                      const float4* __restrict__ w1v,    // 12 floats = 3 x float4
                      const float4* __restrict__ b1v,    // 4 floats
                      const float4* __restrict__ w2v,    // 8 floats = 2 x float4
                      const float2* __restrict__ b2v,    // 2 floats
                      float4*       __restrict__ out,    // [B/2]
                      int nquads)                        // B/4
{
    int i = blockIdx.x * blockDim.x + threadIdx.x;
    if (i >= nquads) return;

    // --- streaming loads first: 6x 128-bit, front-batched (MLP_p1 = 6) ---
    float4 inA = inp[2 * i + 0];
    float4 inB = inp[2 * i + 1];
    float4 d0  = data[4 * i + 0];
    float4 d1  = data[4 * i + 1];
    float4 d2  = data[4 * i + 2];
    float4 d3  = data[4 * i + 3];

    // --- uniform parameter loads (L1-broadcast) ---
    float4 cw   = __ldg(conv_w);
    float  cb   = __ldg(conv_b);
    float4 w1r0 = __ldg(w1v + 0);   // w1[0][*] (in0 weights)
    float4 w1r1 = __ldg(w1v + 1);   // w1[1][*] (in1 weights)
    float4 w1r2 = __ldg(w1v + 2);   // w1[2][*] (conv weights)
    float4 b1   = __ldg(b1v);
    float4 w2a  = __ldg(w2v + 0);   // (w2[0][0], w2[0][1], w2[1][0], w2[1][1])
    float4 w2b  = __ldg(w2v + 1);   // (w2[2][0], w2[2][1], w2[3][0], w2[3][1])
    float2 b2   = __ldg(b2v);

    // One-time fold: output layer delta weights. w2a/w2b/b2 die here.
    float g0 = w2a.y - w2a.x;
    float g1 = w2a.w - w2a.z;
    float g2 = w2b.y - w2b.x;
    float g3 = w2b.w - w2b.z;
    float gb = b2.y  - b2.x;

    float4 resA, resB;

#pragma unroll
    for (int s = 0; s < 4; ++s) {
        float in0, in1;
        float4 d;
        if      (s == 0) { in0 = inA.x; in1 = inA.y; d = d0; }
        else if (s == 1) { in0 = inA.z; in1 = inA.w; d = d1; }
        else if (s == 2) { in0 = inB.x; in1 = inB.y; d = d2; }
        else             { in0 = inB.z; in1 = inB.w; d = d3; }

        // conv 2x2 -> sigmoid via tanh identity (THRESHOLD = 0)
        float logit = fmaf(d.x, cw.x, fmaf(d.y, cw.y,
                      fmaf(d.z, cw.z, fmaf(d.w, cw.w, cb))));
        float conv = fmaf(tanh_fast(0.5f * logit), 0.5f, 0.5f);

        // h = tanh([in0, in1, conv] @ w1 + b1)
        float h0 = tanh_fast(fmaf(in0, w1r0.x, fmaf(in1, w1r1.x, fmaf(conv, w1r2.x, b1.x))));
        float h1 = tanh_fast(fmaf(in0, w1r0.y, fmaf(in1, w1r1.y, fmaf(conv, w1r2.y, b1.y))));
        float h2 = tanh_fast(fmaf(in0, w1r0.z, fmaf(in1, w1r1.z, fmaf(conv, w1r2.z, b1.z))));
        float h3 = tanh_fast(fmaf(in0, w1r0.w, fmaf(in1, w1r1.w, fmaf(conv, w1r2.w, b1.w))));

        // dz = z1 - z0 via folded delta weights
        float dz = fmaf(h0, g0, fmaf(h1, g1, fmaf(h2, g2, fmaf(h3, g3, gb))));

        // softmax over 2 from the difference (exact, same formula as before)
        float e = __expf(dz);
        float r = 1.0f / (1.0f + e);
        float o0 = r, o1 = e * r;

        if      (s == 0) { resA.x = o0; resA.y = o1; }
        else if (s == 1) { resA.z = o0; resA.w = o1; }
        else if (s == 2) { resB.x = o0; resB.y = o1; }
        else             { resB.z = o0; resB.w = o1; }
    }

    out[2 * i + 0] = resA;
    out[2 * i + 1] = resB;
}

extern "C" void kernel_launch(void* const* d_in, const int* in_sizes, int n_in,
                              void* d_out, int out_size)
{
    const float* inp    = (const float*)d_in[0]; // [B,2]
    const float* data   = (const float*)d_in[1]; // [B,2,2]
    const float* conv_w = (const float*)d_in[2];
    const float* conv_b = (const float*)d_in[3];
    const float* w1     = (const float*)d_in[4];
    const float* b1     = (const float*)d_in[5];
    const float* w2     = (const float*)d_in[6];
    const float* b2     = (const float*)d_in[7];
    float* out          = (float*)d_out;

    int B = in_sizes[0] / 2;   // samples
    int nquads = B / 4;        // 4 samples per thread

    int threads = 256;
    int blocks = (nquads + threads - 1) / threads;

    hybrid_sampler_kernel<<<blocks, threads>>>(
        (const float4*)inp, (const float4*)data,
        (const float4*)conv_w, conv_b,
        (const float4*)w1, (const float4*)b1,
        (const float4*)w2, (const float2*)b2,
        (float4*)out, nquads);
}